// round 3
// baseline (speedup 1.0000x reference)
#include <cuda_runtime.h>
#include <cuda_fp16.h>
#include <cstdint>

// Q4 group-quantized linear: out = x @ W^T + bias
// HARNESS DTYPES: fp16 tensors are promoted to float32 by the harness.
//   x:       [8192*4096]  float32
//   qweight: [22544384]   int32 (one packed byte each: 2 nibbles)
//   scales:  [352256]     float32
//   zeros:   [352256]     float32
//   bias:    [11008]      float32
//   out:     [8192*11008] float32
//
// Fused dequant + GEMM. CTA tile 128x128, BK=64, 8 warps (2 M x 4 N),
// warp tile 64x32 via mma.sync.m16n8k16 (fp16 in, fp32 acc).

#define M_TOTAL 8192
#define K_TOTAL 4096
#define N_TOTAL 11008
#define BM 128
#define BN 128
#define BK 64
#define LDS_PAD 8
#define LDS (BK + LDS_PAD)   // 72 halves per smem row -> 144B stride, conflict-free ldmatrix

__global__ __launch_bounds__(256, 2)
void q4gemm_kernel(const float* __restrict__ x,
                   const int*   __restrict__ qw,
                   const float* __restrict__ scales,
                   const float* __restrict__ zeros,
                   const float* __restrict__ bias,
                   float*       __restrict__ out)
{
    __shared__ __half sA[BM][LDS];
    __shared__ __half sB[BN][LDS];

    const int bn = blockIdx.x;
    const int bm = blockIdx.y;
    const int tid  = threadIdx.x;
    const int wid  = tid >> 5;
    const int lane = tid & 31;
    const int warp_m = wid & 1;   // 0..1
    const int warp_n = wid >> 1;  // 0..3

    const int m0 = bm * BM;
    const int n0 = bn * BN;

    float acc[4][4][4];
    #pragma unroll
    for (int mi = 0; mi < 4; ++mi)
        #pragma unroll
        for (int ni = 0; ni < 4; ++ni)
            #pragma unroll
            for (int r = 0; r < 4; ++r)
                acc[mi][ni][r] = 0.0f;

    // B-dequant per-thread constants: 2 threads per tile row, 16 int32 (bytes) each
    const int br = tid >> 1;       // tile row (n direction), 0..127
    const int bh = tid & 1;        // which 16-byte half of the 32-byte k-slab
    const int gn = n0 + br;        // global output row

    const int NKT = K_TOTAL / BK;  // 64 k-tiles

    for (int kt = 0; kt < NKT; ++kt) {
        const int k0 = kt * BK;

        // ---- load A tile (128 x 64 fp32 -> fp16 in smem) ----
        // 8192 floats / 256 threads = 32 floats = 8 x float4 per thread
        #pragma unroll
        for (int i = 0; i < 8; ++i) {
            int u = tid + i * 256;          // 0..2047 (float4 chunks)
            int r = u >> 4;                 // row 0..127 (16 float4 per row)
            int c = (u & 15) << 2;          // col 0..60
            float4 v = *(const float4*)&x[(size_t)(m0 + r) * K_TOTAL + k0 + c];
            __half2 h0 = __floats2half2_rn(v.x, v.y);
            __half2 h1 = __floats2half2_rn(v.z, v.w);
            *(__half2*)&sA[r][c]     = h0;
            *(__half2*)&sA[r][c + 2] = h1;
        }

        // ---- dequant B tile (128 rows x 64 k) ----
        {
            // group: g = n*32 + k/128; whole BK=64 slab is in one group
            const int g = gn * (K_TOTAL / 128) + (k0 >> 7);
            const float s = scales[g];
            const float z = zeros[g];

            const int* src = qw + (size_t)gn * (K_TOTAL / 2) + (k0 >> 1) + bh * 16;
            int4 v0 = ((const int4*)src)[0];
            int4 v1 = ((const int4*)src)[1];
            int4 v2 = ((const int4*)src)[2];
            int4 v3 = ((const int4*)src)[3];
            int vals[16] = { v0.x, v0.y, v0.z, v0.w,
                             v1.x, v1.y, v1.z, v1.w,
                             v2.x, v2.y, v2.z, v2.w,
                             v3.x, v3.y, v3.z, v3.w };
            __half hbuf[32];
            #pragma unroll
            for (int j = 0; j < 16; ++j) {
                int b  = vals[j] & 0xFF;
                float lo = (float)((b & 15) - 8)        * s + z;
                float hi = (float)(((b >> 4) & 15) - 8) * s + z;
                hbuf[2 * j]     = __float2half(lo);
                hbuf[2 * j + 1] = __float2half(hi);
            }
            const int kbase = bh * 32;
            #pragma unroll
            for (int q = 0; q < 4; ++q)
                *(uint4*)&sB[br][kbase + q * 8] = *(uint4*)&hbuf[q * 8];
        }

        __syncthreads();

        // ---- compute: 4 k-steps of m16n8k16 ----
        #pragma unroll
        for (int ks = 0; ks < 4; ++ks) {
            uint32_t af[4][4];
            uint32_t bf[4][2];

            #pragma unroll
            for (int mi = 0; mi < 4; ++mi) {
                int row = warp_m * 64 + mi * 16 + (lane & 15);
                int col = ks * 16 + ((lane >> 4) << 3);
                uint32_t addr = (uint32_t)__cvta_generic_to_shared(&sA[row][col]);
                asm volatile(
                    "ldmatrix.sync.aligned.m8n8.x4.shared.b16 {%0,%1,%2,%3}, [%4];"
                    : "=r"(af[mi][0]), "=r"(af[mi][1]), "=r"(af[mi][2]), "=r"(af[mi][3])
                    : "r"(addr));
            }
            #pragma unroll
            for (int ni = 0; ni < 4; ++ni) {
                int row = warp_n * 32 + ni * 8 + (lane & 7);
                int col = ks * 16 + (((lane >> 3) & 1) << 3);
                uint32_t addr = (uint32_t)__cvta_generic_to_shared(&sB[row][col]);
                asm volatile(
                    "ldmatrix.sync.aligned.m8n8.x2.shared.b16 {%0,%1}, [%2];"
                    : "=r"(bf[ni][0]), "=r"(bf[ni][1])
                    : "r"(addr));
            }
            #pragma unroll
            for (int mi = 0; mi < 4; ++mi)
                #pragma unroll
                for (int ni = 0; ni < 4; ++ni)
                    asm volatile(
                        "mma.sync.aligned.m16n8k16.row.col.f32.f16.f16.f32 "
                        "{%0,%1,%2,%3}, {%4,%5,%6,%7}, {%8,%9}, {%0,%1,%2,%3};"
                        : "+f"(acc[mi][ni][0]), "+f"(acc[mi][ni][1]),
                          "+f"(acc[mi][ni][2]), "+f"(acc[mi][ni][3])
                        : "r"(af[mi][0]), "r"(af[mi][1]), "r"(af[mi][2]), "r"(af[mi][3]),
                          "r"(bf[ni][0]), "r"(bf[ni][1]));
        }

        __syncthreads();
    }

    // ---- epilogue: add bias, store fp32 ----
    #pragma unroll
    for (int mi = 0; mi < 4; ++mi) {
        #pragma unroll
        for (int ni = 0; ni < 4; ++ni) {
            int m = m0 + warp_m * 64 + mi * 16 + (lane >> 2);
            int n = n0 + warp_n * 32 + ni * 8 + (lane & 3) * 2;
            float b0 = bias[n];
            float b1 = bias[n + 1];
            // match reference: fp16 rounding of (acc + bias), output promoted to fp32
            float2 r0 = make_float2(__half2float(__float2half(acc[mi][ni][0] + b0)),
                                    __half2float(__float2half(acc[mi][ni][1] + b1)));
            float2 r1 = make_float2(__half2float(__float2half(acc[mi][ni][2] + b0)),
                                    __half2float(__float2half(acc[mi][ni][3] + b1)));
            *(float2*)&out[(size_t)m * N_TOTAL + n]       = r0;
            *(float2*)&out[(size_t)(m + 8) * N_TOTAL + n] = r1;
        }
    }
}

extern "C" void kernel_launch(void* const* d_in, const int* in_sizes, int n_in,
                              void* d_out, int out_size)
{
    const float* x      = (const float*)d_in[0];
    const int*   qw     = (const int*)  d_in[1];
    const float* scales = (const float*)d_in[2];
    const float* zeros  = (const float*)d_in[3];
    const float* bias   = (const float*)d_in[4];
    float*       out    = (float*)d_out;

    dim3 grid(N_TOTAL / BN, M_TOTAL / BM);   // 86 x 64
    q4gemm_kernel<<<grid, 256>>>(x, qw, scales, zeros, bias, out);
}

// round 4
// speedup vs baseline: 1.4420x; 1.4420x over previous
#include <cuda_runtime.h>
#include <cuda_fp16.h>
#include <cstdint>

// Q4 group-quantized linear: out = x @ W^T + bias   (all harness tensors fp32/int32)
//   x: [8192,4096] f32   qweight: [22544384] i32 (1 byte each)
//   scales/zeros: [352256] f32   bias: [11008] f32   out: [8192,11008] f32
//
// Round 4 plan:
//  1) preprocess: x -> fp16 scratch, qweight -> packed uint8 scratch
//  2) fused dequant GEMM, 2-stage cp.async pipeline, LOP3 nibble->fp16 dequant
//     CTA 128x128, BK=64, 8 warps (2x4), warp tile 64x32, mma.m16n8k16 f16->f32

#define M_TOTAL 8192
#define K_TOTAL 4096
#define N_TOTAL 11008
#define BM 128
#define BN 128
#define BK 64
#define LDS 72                       // 72 halves/row = 144B stride, ldmatrix conflict-free
#define STAGE_HALVES (BM * LDS)      // 9216
#define SMEM_BYTES (2 * 2 * STAGE_HALVES * 2)   // 2 stages x (A+B) x 9216 halves x 2B = 73728

// ---- scratch (device globals; no runtime allocation) ----
__device__ __align__(16) __half  g_x16[(size_t)M_TOTAL * K_TOTAL];        // 64 MB
__device__ __align__(16) uint8_t g_qw8[(size_t)N_TOTAL * (K_TOTAL / 2)];  // 22.5 MB

// ---- preprocess: fp32 x -> fp16 ----
__global__ void convert_x_kernel(const float* __restrict__ x) {
    size_t idx = (size_t)blockIdx.x * blockDim.x + threadIdx.x;  // one per 8 halves
    size_t base = idx * 8;
    float4 a = *(const float4*)&x[base];
    float4 b = *(const float4*)&x[base + 4];
    __half2 h[4] = { __floats2half2_rn(a.x, a.y), __floats2half2_rn(a.z, a.w),
                     __floats2half2_rn(b.x, b.y), __floats2half2_rn(b.z, b.w) };
    *(uint4*)&g_x16[base] = *(uint4*)h;
}

// ---- preprocess: int32-per-byte qweight -> packed uint8 ----
__global__ void repack_qw_kernel(const int* __restrict__ qw) {
    size_t idx = (size_t)blockIdx.x * blockDim.x + threadIdx.x;  // one per 4 bytes
    int4 v = ((const int4*)qw)[idx];
    uint32_t packed = (uint32_t)(v.x & 0xFF) | ((uint32_t)(v.y & 0xFF) << 8) |
                      ((uint32_t)(v.z & 0xFF) << 16) | ((uint32_t)(v.w & 0xFF) << 24);
    ((uint32_t*)g_qw8)[idx] = packed;
}

// dequant 4 packed bytes (8 nibbles) -> 4 half2, w = (n-8)*s + z
__device__ __forceinline__ void dq4(uint32_t v, __half2 s2, __half2 z2, __half2 k1032,
                                    __half2* o) {
    uint32_t b0 = 0x64006400u | (v & 0xFu)         | ((v & 0xF0u) << 12);
    uint32_t b1 = 0x64006400u | ((v >> 8) & 0xFu)  | ((v & 0xF000u) << 4);
    uint32_t b2 = 0x64006400u | ((v >> 16) & 0xFu) | ((v & 0xF00000u) >> 4);
    uint32_t b3 = 0x64006400u | ((v >> 24) & 0xFu) | ((v & 0xF0000000u) >> 12);
    o[0] = __hfma2(__hsub2(*(__half2*)&b0, k1032), s2, z2);
    o[1] = __hfma2(__hsub2(*(__half2*)&b1, k1032), s2, z2);
    o[2] = __hfma2(__hsub2(*(__half2*)&b2, k1032), s2, z2);
    o[3] = __hfma2(__hsub2(*(__half2*)&b3, k1032), s2, z2);
}

__global__ __launch_bounds__(256, 2)
void q4gemm_kernel(const float* __restrict__ scales,
                   const float* __restrict__ zeros,
                   const float* __restrict__ bias,
                   float*       __restrict__ out)
{
    extern __shared__ __half smem[];
    __half* sA = smem;                       // [2][BM][LDS]
    __half* sB = smem + 2 * STAGE_HALVES;    // [2][BN][LDS]

    const int bn = blockIdx.x;
    const int bm = blockIdx.y;
    const int tid  = threadIdx.x;
    const int wid  = tid >> 5;
    const int lane = tid & 31;
    const int warp_m = wid & 1;
    const int warp_n = wid >> 1;

    const int m0 = bm * BM;
    const int n0 = bn * BN;

    float acc[4][4][4];
    #pragma unroll
    for (int mi = 0; mi < 4; ++mi)
        #pragma unroll
        for (int ni = 0; ni < 4; ++ni)
            #pragma unroll
            for (int r = 0; r < 4; ++r)
                acc[mi][ni][r] = 0.0f;

    // B-dequant roles: 2 threads/row, 16 packed bytes (32 weights) each
    const int br = tid >> 1;
    const int bh = tid & 1;
    const int gn = n0 + br;
    const __half2 k1032 = __floats2half2_rn(1032.0f, 1032.0f);
    const uint8_t* qrow = g_qw8 + (size_t)gn * (K_TOTAL / 2) + bh * 16;

    const int NKT = K_TOTAL / BK;

    // A cp.async: 4 x 16B per thread per stage
    auto issue_a = [&](int kt, int st) {
        const __half* src_base = g_x16 + (size_t)m0 * K_TOTAL + kt * BK;
        __half* dst_base = sA + st * STAGE_HALVES;
        #pragma unroll
        for (int i = 0; i < 4; ++i) {
            int u = tid + i * 256;       // 0..1023 chunks of 8 halves
            int r = u >> 3;
            int c = (u & 7) << 3;
            uint32_t daddr = (uint32_t)__cvta_generic_to_shared(dst_base + r * LDS + c);
            const __half* gsrc = src_base + (size_t)r * K_TOTAL + c;
            asm volatile("cp.async.cg.shared.global [%0], [%1], 16;\n"
                         :: "r"(daddr), "l"(gsrc));
        }
        asm volatile("cp.async.commit_group;\n");
    };

    auto dequant_store = [&](int kt, int st, uint4 qv) {
        const int g = gn * (K_TOTAL / 128) + ((kt * BK) >> 7);
        const __half2 s2 = __float2half2_rn(scales[g]);
        const __half2 z2 = __float2half2_rn(zeros[g]);
        __half2 hb[16];
        dq4(qv.x, s2, z2, k1032, hb + 0);
        dq4(qv.y, s2, z2, k1032, hb + 4);
        dq4(qv.z, s2, z2, k1032, hb + 8);
        dq4(qv.w, s2, z2, k1032, hb + 12);
        __half* dst = sB + st * STAGE_HALVES + br * LDS + bh * 32;
        #pragma unroll
        for (int q = 0; q < 4; ++q)
            *(uint4*)(dst + q * 8) = *(uint4*)(hb + q * 4);
    };

    // ---- prologue: stage 0 ----
    issue_a(0, 0);
    {
        uint4 qv = *(const uint4*)(qrow + 0);
        dequant_store(0, 0, qv);
    }
    asm volatile("cp.async.wait_group 0;\n");
    __syncthreads();

    for (int kt = 0; kt < NKT; ++kt) {
        const int cur = kt & 1;
        const int nxt = cur ^ 1;

        uint4 qv;
        if (kt + 1 < NKT) {
            issue_a(kt + 1, nxt);
            qv = *(const uint4*)(qrow + (size_t)(kt + 1) * (BK / 2));
        }

        // ---- compute on cur ----
        const __half* cA = sA + cur * STAGE_HALVES;
        const __half* cB = sB + cur * STAGE_HALVES;
        #pragma unroll
        for (int ks = 0; ks < 4; ++ks) {
            uint32_t af[4][4];
            uint32_t bf[4][2];
            #pragma unroll
            for (int mi = 0; mi < 4; ++mi) {
                int row = warp_m * 64 + mi * 16 + (lane & 15);
                int col = ks * 16 + ((lane >> 4) << 3);
                uint32_t addr = (uint32_t)__cvta_generic_to_shared(cA + row * LDS + col);
                asm volatile(
                    "ldmatrix.sync.aligned.m8n8.x4.shared.b16 {%0,%1,%2,%3}, [%4];"
                    : "=r"(af[mi][0]), "=r"(af[mi][1]), "=r"(af[mi][2]), "=r"(af[mi][3])
                    : "r"(addr));
            }
            #pragma unroll
            for (int ni = 0; ni < 4; ++ni) {
                int row = warp_n * 32 + ni * 8 + (lane & 7);
                int col = ks * 16 + (((lane >> 3) & 1) << 3);
                uint32_t addr = (uint32_t)__cvta_generic_to_shared(cB + row * LDS + col);
                asm volatile(
                    "ldmatrix.sync.aligned.m8n8.x2.shared.b16 {%0,%1}, [%2];"
                    : "=r"(bf[ni][0]), "=r"(bf[ni][1])
                    : "r"(addr));
            }
            #pragma unroll
            for (int mi = 0; mi < 4; ++mi)
                #pragma unroll
                for (int ni = 0; ni < 4; ++ni)
                    asm volatile(
                        "mma.sync.aligned.m16n8k16.row.col.f32.f16.f16.f32 "
                        "{%0,%1,%2,%3}, {%4,%5,%6,%7}, {%8,%9}, {%0,%1,%2,%3};"
                        : "+f"(acc[mi][ni][0]), "+f"(acc[mi][ni][1]),
                          "+f"(acc[mi][ni][2]), "+f"(acc[mi][ni][3])
                        : "r"(af[mi][0]), "r"(af[mi][1]), "r"(af[mi][2]), "r"(af[mi][3]),
                          "r"(bf[ni][0]), "r"(bf[ni][1]));
        }

        if (kt + 1 < NKT) {
            dequant_store(kt + 1, nxt, qv);
            asm volatile("cp.async.wait_group 0;\n");
        }
        __syncthreads();
    }

    // ---- epilogue: bias + fp16-rounding to match reference, store fp32 ----
    #pragma unroll
    for (int mi = 0; mi < 4; ++mi) {
        #pragma unroll
        for (int ni = 0; ni < 4; ++ni) {
            int m = m0 + warp_m * 64 + mi * 16 + (lane >> 2);
            int n = n0 + warp_n * 32 + ni * 8 + (lane & 3) * 2;
            float b0 = bias[n];
            float b1 = bias[n + 1];
            float2 r0 = make_float2(__half2float(__float2half(acc[mi][ni][0] + b0)),
                                    __half2float(__float2half(acc[mi][ni][1] + b1)));
            float2 r1 = make_float2(__half2float(__float2half(acc[mi][ni][2] + b0)),
                                    __half2float(__float2half(acc[mi][ni][3] + b1)));
            *(float2*)&out[(size_t)m * N_TOTAL + n]       = r0;
            *(float2*)&out[(size_t)(m + 8) * N_TOTAL + n] = r1;
        }
    }
}

extern "C" void kernel_launch(void* const* d_in, const int* in_sizes, int n_in,
                              void* d_out, int out_size)
{
    const float* x      = (const float*)d_in[0];
    const int*   qw     = (const int*)  d_in[1];
    const float* scales = (const float*)d_in[2];
    const float* zeros  = (const float*)d_in[3];
    const float* bias   = (const float*)d_in[4];
    float*       out    = (float*)d_out;

    cudaFuncSetAttribute(q4gemm_kernel,
                         cudaFuncAttributeMaxDynamicSharedMemorySize, SMEM_BYTES);

    // preprocess
    convert_x_kernel<<<(M_TOTAL * (size_t)K_TOTAL) / 8 / 256, 256>>>(x);   // 16384 blocks
    repack_qw_kernel<<<22544384 / 4 / 256, 256>>>(qw);                     // 22016 blocks

    dim3 grid(N_TOTAL / BN, M_TOTAL / BM);   // 86 x 64
    q4gemm_kernel<<<grid, 256, SMEM_BYTES>>>(scales, zeros, bias, out);
}